// round 2
// baseline (speedup 1.0000x reference)
#include <cuda_runtime.h>

// Problem constants
#define NE 8
#define NR 64
#define ND 2048
#define NT 16384            // B*S tokens
#define TILE_M 128
#define ORDER_SZ (NT + NE * TILE_M)       // padded order array (segments 128-aligned)
#define MAX_TILES (ORDER_SZ / TILE_M)     // 136
#define KC 32               // k-chunk for phase 1
#define DC 64               // d-chunk for phase 2

// Dynamic smem layout (floats):
//   [0 .. P1_F)        phase1: xs[TILE_M][KC+1], as[NR][KC+1]  (aliased in phase2 by bs[NR][DC+1])
//   [P1_F .. +HS_F)    Hs[NR][TILE_M+1]
#define XS_F (TILE_M * (KC + 1))          // 128*33 = 4224
#define AS_F (NR * (KC + 1))              // 64*33  = 2112
#define P1_F (XS_F + AS_F)                // 6336
#define BS_F (NR * (DC + 1))              // 64*65  = 4160  (< P1_F, fits in alias)
#define HS_F (NR * (TILE_M + 1))          // 64*129 = 8256
#define SMEM_FLOATS (P1_F + HS_F)         // 14592
#define SMEM_BYTES (SMEM_FLOATS * 4)      // 58368

// -------- grouping state (device globals; re-initialized every launch) --------
__device__ int g_counts[NE];
__device__ int g_base[NE];
__device__ int g_order[ORDER_SZ];
__device__ int g_tile_expert[MAX_TILES];

__global__ void k_init() {
    int i = blockIdx.x * blockDim.x + threadIdx.x;
    if (i < ORDER_SZ) g_order[i] = -1;
    if (i < NE) g_counts[i] = 0;
    if (i < MAX_TILES) g_tile_expert[i] = -1;
}

__global__ void k_hist(const int* __restrict__ idx) {
    __shared__ int s_cnt[NE];
    int tid = threadIdx.x;
    if (tid < NE) s_cnt[tid] = 0;
    __syncthreads();
    int t = blockIdx.x * blockDim.x + tid;
    atomicAdd(&s_cnt[idx[t]], 1);
    __syncthreads();
    if (tid < NE && s_cnt[tid] > 0) atomicAdd(&g_counts[tid], s_cnt[tid]);
}

__global__ void k_scan() {
    // single thread: 8 experts, <=136 tile slots
    int off = 0, tile = 0;
    for (int e = 0; e < NE; ++e) {
        g_base[e] = off;
        int nt = (g_counts[e] + TILE_M - 1) / TILE_M;
        for (int j = 0; j < nt; ++j) g_tile_expert[tile++] = e;
        off += nt * TILE_M;
    }
}

__global__ void k_scatter(const int* __restrict__ idx) {
    __shared__ int s_cnt[NE], s_base[NE];
    int tid = threadIdx.x;
    if (tid < NE) s_cnt[tid] = 0;
    __syncthreads();
    int t = blockIdx.x * blockDim.x + tid;
    int e = idx[t];
    int lp = atomicAdd(&s_cnt[e], 1);
    __syncthreads();
    if (tid < NE) s_base[tid] = (s_cnt[tid] > 0) ? atomicAdd(&g_base[tid], s_cnt[tid]) : 0;
    __syncthreads();
    g_order[s_base[e] + lp] = t;
}

// -------- fused low-rank adapter GEMM: one 128-token, single-expert tile per block --------
__global__ __launch_bounds__(256, 1) void k_lora(
    const float* __restrict__ x, const float* __restrict__ Aw,
    const float* __restrict__ Bw, float* __restrict__ out) {
    extern __shared__ float sm[];
    float (*xs)[KC + 1]     = (float (*)[KC + 1])sm;
    float (*as)[KC + 1]     = (float (*)[KC + 1])(sm + XS_F);
    float (*bs)[DC + 1]     = (float (*)[DC + 1])sm;          // aliases xs/as (phase 2)
    float (*Hs)[TILE_M + 1] = (float (*)[TILE_M + 1])(sm + P1_F);
    __shared__ int s_tok[TILE_M];

    const int e = g_tile_expert[blockIdx.x];
    if (e < 0) return;
    const int tid = threadIdx.x;
    if (tid < TILE_M) s_tok[tid] = g_order[blockIdx.x * TILE_M + tid];
    __syncthreads();

    const int tm = tid >> 4;       // 0..15 -> token sub-block base tm*8
    const int tn = tid & 15;       // 0..15 -> r (phase1) / d (phase2) base tn*4
    const int m0 = tm * 8;
    const float* Ae = Aw + e * NR * ND;
    const float* Be = Bw + e * ND * NR;

    // ---------------- Phase 1: H[128][64] = X_tile @ A_e^T ----------------
    float acc[8][4];
#pragma unroll
    for (int i = 0; i < 8; ++i)
#pragma unroll
        for (int j = 0; j < 4; ++j) acc[i][j] = 0.f;

    for (int k0 = 0; k0 < ND; k0 += KC) {
        // gather x chunk: 128 tokens x 32 k, float4 loads (8 f4 per row)
#pragma unroll
        for (int i = tid; i < TILE_M * (KC / 4); i += 256) {
            int m = i >> 3, k = (i & 7) * 4;
            int t = s_tok[m];
            float4 v = (t >= 0) ? *(const float4*)(x + (size_t)t * ND + k0 + k)
                                : make_float4(0.f, 0.f, 0.f, 0.f);
            xs[m][k + 0] = v.x; xs[m][k + 1] = v.y;
            xs[m][k + 2] = v.z; xs[m][k + 3] = v.w;
        }
        // A chunk: 64 r x 32 k, float4 loads
#pragma unroll
        for (int i = tid; i < NR * (KC / 4); i += 256) {
            int r = i >> 3, k = (i & 7) * 4;
            float4 v = *(const float4*)(Ae + r * ND + k0 + k);
            as[r][k + 0] = v.x; as[r][k + 1] = v.y;
            as[r][k + 2] = v.z; as[r][k + 3] = v.w;
        }
        __syncthreads();
#pragma unroll
        for (int k = 0; k < KC; ++k) {
            float xv[8], av[4];
#pragma unroll
            for (int i = 0; i < 8; ++i) xv[i] = xs[m0 + i][k];
#pragma unroll
            for (int j = 0; j < 4; ++j) av[j] = as[tn * 4 + j][k];
#pragma unroll
            for (int i = 0; i < 8; ++i)
#pragma unroll
                for (int j = 0; j < 4; ++j) acc[i][j] += xv[i] * av[j];
        }
        __syncthreads();
    }
    // spill H to smem (transposed: Hs[r][m])
#pragma unroll
    for (int i = 0; i < 8; ++i)
#pragma unroll
        for (int j = 0; j < 4; ++j) Hs[tn * 4 + j][m0 + i] = acc[i][j];
    __syncthreads();

    // ---------------- Phase 2: OUT[128][2048] = H @ B_e^T ----------------
    for (int d0 = 0; d0 < ND; d0 += DC) {
        // B chunk -> bs[r][d]; float4 over contiguous r (coalesced)
#pragma unroll
        for (int i = tid; i < DC * (NR / 4); i += 256) {
            int r = (i & 15) * 4, d = i >> 4;
            float4 v = *(const float4*)(Be + (d0 + d) * NR + r);
            bs[r + 0][d] = v.x; bs[r + 1][d] = v.y;
            bs[r + 2][d] = v.z; bs[r + 3][d] = v.w;
        }
        __syncthreads();

        float acc2[8][4];
#pragma unroll
        for (int i = 0; i < 8; ++i)
#pragma unroll
            for (int j = 0; j < 4; ++j) acc2[i][j] = 0.f;

#pragma unroll 8
        for (int r = 0; r < NR; ++r) {
            float hv[8], bv[4];
#pragma unroll
            for (int i = 0; i < 8; ++i) hv[i] = Hs[r][m0 + i];
#pragma unroll
            for (int j = 0; j < 4; ++j) bv[j] = bs[r][tn * 4 + j];
#pragma unroll
            for (int i = 0; i < 8; ++i)
#pragma unroll
                for (int j = 0; j < 4; ++j) acc2[i][j] += hv[i] * bv[j];
        }

        // float4 stores: 4 consecutive d per thread, 16B aligned
#pragma unroll
        for (int i = 0; i < 8; ++i) {
            int t = s_tok[m0 + i];
            if (t >= 0) {
                float4 v = make_float4(acc2[i][0], acc2[i][1], acc2[i][2], acc2[i][3]);
                *(float4*)(out + (size_t)t * ND + d0 + tn * 4) = v;
            }
        }
        __syncthreads();
    }
}

extern "C" void kernel_launch(void* const* d_in, const int* in_sizes, int n_in,
                              void* d_out, int out_size) {
    const float* x   = (const float*)d_in[0];
    const float* Aw  = (const float*)d_in[1];
    const float* Bw  = (const float*)d_in[2];
    const int*   idx = (const int*)d_in[3];
    float* out = (float*)d_out;

    cudaFuncSetAttribute(k_lora, cudaFuncAttributeMaxDynamicSharedMemorySize, SMEM_BYTES);

    k_init<<<(ORDER_SZ + 1023) / 1024, 1024>>>();
    k_hist<<<NT / 1024, 1024>>>(idx);
    k_scan<<<1, 1>>>();
    k_scatter<<<NT / 1024, 1024>>>(idx);
    k_lora<<<MAX_TILES, 256, SMEM_BYTES>>>(x, Aw, Bw, out);
}

// round 3
// speedup vs baseline: 1.5519x; 1.5519x over previous
#include <cuda_runtime.h>
#include <cuda_bf16.h>
#include <cstdint>

// Problem constants
#define NE 8
#define NR 64
#define ND 2048
#define NT 16384            // B*S tokens
#define TILE_M 128
#define ORDER_SZ (NT + NE * TILE_M)
#define MAX_TILES (ORDER_SZ / TILE_M)     // 136
#define WSZ (NE * NR * ND)                // 1048576 weight elems (A and B each)
#define KC 64                              // phase-1 K chunk
#define DC 128                             // phase-2 D chunk
#define SMS 72                             // smem row stride in halves (bank-safe for ldmatrix)

// smem layout (half indices); phase2 B aliases phase1 x region
#define XH_H 0
#define XL_H (XH_H + TILE_M * SMS)        // 9216
#define AH_H (XL_H + TILE_M * SMS)        // 18432
#define AL_H (AH_H + NR * SMS)            // 23040
#define HH_H (AL_H + NR * SMS)            // 27648
#define HL_H (HH_H + TILE_M * SMS)        // 36864
#define SMEM_HALVES (HL_H + TILE_M * SMS) // 46080
#define SMEM_BYTES (SMEM_HALVES * 2)      // 92160
#define BH_H XH_H
#define BL_H XL_H

// -------- grouping state + split weights (device globals) --------
__device__ int g_counts[NE];
__device__ int g_base[NE];
__device__ int g_order[ORDER_SZ];
__device__ int g_tile_expert[MAX_TILES];
__device__ __nv_bfloat16 g_Ah[WSZ], g_Al[WSZ];
__device__ __nv_bfloat16 g_Bh[WSZ], g_Bl[WSZ];

__global__ void k_init() {
    int i = blockIdx.x * blockDim.x + threadIdx.x;
    if (i < ORDER_SZ) g_order[i] = -1;
    if (i < NE) g_counts[i] = 0;
    if (i < MAX_TILES) g_tile_expert[i] = -1;
}

__global__ void k_hist(const int* __restrict__ idx) {
    __shared__ int s_cnt[NE];
    int tid = threadIdx.x;
    if (tid < NE) s_cnt[tid] = 0;
    __syncthreads();
    int t = blockIdx.x * blockDim.x + tid;
    atomicAdd(&s_cnt[idx[t]], 1);
    __syncthreads();
    if (tid < NE && s_cnt[tid] > 0) atomicAdd(&g_counts[tid], s_cnt[tid]);
}

__global__ void k_scan() {
    int off = 0, tile = 0;
    for (int e = 0; e < NE; ++e) {
        g_base[e] = off;
        int nt = (g_counts[e] + TILE_M - 1) / TILE_M;
        for (int j = 0; j < nt; ++j) g_tile_expert[tile++] = e;
        off += nt * TILE_M;
    }
}

__global__ void k_scatter(const int* __restrict__ idx) {
    __shared__ int s_cnt[NE], s_base[NE];
    int tid = threadIdx.x;
    if (tid < NE) s_cnt[tid] = 0;
    __syncthreads();
    int t = blockIdx.x * blockDim.x + tid;
    int e = idx[t];
    int lp = atomicAdd(&s_cnt[e], 1);
    __syncthreads();
    if (tid < NE) s_base[tid] = (s_cnt[tid] > 0) ? atomicAdd(&g_base[tid], s_cnt[tid]) : 0;
    __syncthreads();
    g_order[s_base[e] + lp] = t;
}

// split weights into bf16 hi/lo once per launch
__global__ void k_convW(const float* __restrict__ Aw, const float* __restrict__ Bw) {
    int i = blockIdx.x * blockDim.x + threadIdx.x;
    if (i >= WSZ) return;
    float a = Aw[i];
    __nv_bfloat16 ah = __float2bfloat16(a);
    g_Ah[i] = ah;
    g_Al[i] = __float2bfloat16(a - __bfloat162float(ah));
    float b = Bw[i];
    __nv_bfloat16 bh = __float2bfloat16(b);
    g_Bh[i] = bh;
    g_Bl[i] = __float2bfloat16(b - __bfloat162float(bh));
}

// -------- mma helpers --------
__device__ __forceinline__ void ldsm4(uint32_t* r, uint32_t addr) {
    asm volatile("ldmatrix.sync.aligned.m8n8.x4.shared.b16 {%0,%1,%2,%3}, [%4];"
                 : "=r"(r[0]), "=r"(r[1]), "=r"(r[2]), "=r"(r[3]) : "r"(addr));
}
__device__ __forceinline__ void mma_bf16(float* c, const uint32_t* a, uint32_t b0, uint32_t b1) {
    asm volatile("mma.sync.aligned.m16n8k16.row.col.f32.bf16.bf16.f32 "
                 "{%0,%1,%2,%3}, {%4,%5,%6,%7}, {%8,%9}, {%0,%1,%2,%3};"
                 : "+f"(c[0]), "+f"(c[1]), "+f"(c[2]), "+f"(c[3])
                 : "r"(a[0]), "r"(a[1]), "r"(a[2]), "r"(a[3]), "r"(b0), "r"(b1));
}
__device__ __forceinline__ uint32_t packbf(__nv_bfloat16 a, __nv_bfloat16 b) {
    __nv_bfloat162 t(a, b);
    return *(uint32_t*)&t;
}
__device__ __forceinline__ void split2(float v, __nv_bfloat16& h, __nv_bfloat16& l) {
    h = __float2bfloat16(v);
    l = __float2bfloat16(v - __bfloat162float(h));
}

// -------- fused tile kernel: 128 tokens, one expert, bf16-split tensor-core GEMMs --------
__global__ __launch_bounds__(256, 1) void k_lora(
    const float* __restrict__ x, float* __restrict__ out) {
    extern __shared__ __nv_bfloat16 smh[];
    __shared__ int s_tok[TILE_M];

    const int e = g_tile_expert[blockIdx.x];
    if (e < 0) return;
    const int tid = threadIdx.x;
    const int w = tid >> 5;              // warp 0..7 -> rows 16w..16w+15
    const int lane = tid & 31;
    if (tid < TILE_M) s_tok[tid] = g_order[blockIdx.x * TILE_M + tid];
    __syncthreads();

    const uint32_t sb = (uint32_t)__cvta_generic_to_shared(smh);
    // per-lane ldmatrix byte offsets (relative to fragment origin), stride SMS halves
    const int within = lane & 7, mat = lane >> 3;
    const uint32_t offA = (((within + ((mat & 1) << 3)) * SMS) + ((mat >> 1) << 3)) * 2;
    const uint32_t offB = (((within + ((mat >> 1) << 3)) * SMS) + ((mat & 1) << 3)) * 2;

    const __nv_bfloat16* Ah = g_Ah + e * NR * ND;
    const __nv_bfloat16* Al = g_Al + e * NR * ND;
    const __nv_bfloat16* Bh = g_Bh + e * ND * NR;
    const __nv_bfloat16* Bl = g_Bl + e * ND * NR;

    // ================= Phase 1: H[128][64] = X @ A^T =================
    float acc[8][4];
#pragma unroll
    for (int f = 0; f < 8; ++f)
#pragma unroll
        for (int j = 0; j < 4; ++j) acc[f][j] = 0.f;

    for (int k0 = 0; k0 < ND; k0 += KC) {
        // stage x chunk f32 -> bf16 hi/lo smem [128][SMS]
#pragma unroll
        for (int i = tid; i < TILE_M * (KC / 4); i += 256) {
            int m = i >> 4, c = (i & 15) << 2;
            int t = s_tok[m];
            float4 v = (t >= 0) ? *(const float4*)(x + (size_t)t * ND + k0 + c)
                                : make_float4(0.f, 0.f, 0.f, 0.f);
            __nv_bfloat16 h0, l0, h1, l1, h2, l2, h3, l3;
            split2(v.x, h0, l0); split2(v.y, h1, l1);
            split2(v.z, h2, l2); split2(v.w, h3, l3);
            *(uint2*)&smh[XH_H + m * SMS + c] = make_uint2(packbf(h0, h1), packbf(h2, h3));
            *(uint2*)&smh[XL_H + m * SMS + c] = make_uint2(packbf(l0, l1), packbf(l2, l3));
        }
        // stage A chunk bf16 hi/lo [64][SMS]
#pragma unroll
        for (int i = tid; i < NR * (KC / 4); i += 256) {
            int r = i >> 4, c = (i & 15) << 2;
            *(uint2*)&smh[AH_H + r * SMS + c] = *(const uint2*)(Ah + r * ND + k0 + c);
            *(uint2*)&smh[AL_H + r * SMS + c] = *(const uint2*)(Al + r * ND + k0 + c);
        }
        __syncthreads();

#pragma unroll
        for (int kk = 0; kk < KC / 16; ++kk) {
            uint32_t ah[4], al[4];
            uint32_t abase = (w * 16 * SMS + kk * 16) * 2;
            ldsm4(ah, sb + XH_H * 2 + abase + offA);
            ldsm4(al, sb + XL_H * 2 + abase + offA);
#pragma unroll
            for (int g = 0; g < 4; ++g) {          // n-groups of 16 (r dim)
                uint32_t bh[4], bl[4];
                uint32_t bbase = (g * 16 * SMS + kk * 16) * 2;
                ldsm4(bh, sb + AH_H * 2 + bbase + offB);
                ldsm4(bl, sb + AL_H * 2 + bbase + offB);
                mma_bf16(acc[2 * g], ah, bh[0], bh[1]);
                mma_bf16(acc[2 * g], ah, bl[0], bl[1]);
                mma_bf16(acc[2 * g], al, bh[0], bh[1]);
                mma_bf16(acc[2 * g + 1], ah, bh[2], bh[3]);
                mma_bf16(acc[2 * g + 1], ah, bl[2], bl[3]);
                mma_bf16(acc[2 * g + 1], al, bh[2], bh[3]);
            }
        }
        __syncthreads();
    }

    // spill H -> smem as bf16 hi/lo [128][SMS]
    {
        int r0 = w * 16 + (lane >> 2);
        int cb = (lane & 3) * 2;
#pragma unroll
        for (int f = 0; f < 8; ++f) {
            int col = 8 * f + cb;
            __nv_bfloat16 h0, l0, h1, l1;
            split2(acc[f][0], h0, l0); split2(acc[f][1], h1, l1);
            *(uint32_t*)&smh[HH_H + r0 * SMS + col] = packbf(h0, h1);
            *(uint32_t*)&smh[HL_H + r0 * SMS + col] = packbf(l0, l1);
            split2(acc[f][2], h0, l0); split2(acc[f][3], h1, l1);
            *(uint32_t*)&smh[HH_H + (r0 + 8) * SMS + col] = packbf(h0, h1);
            *(uint32_t*)&smh[HL_H + (r0 + 8) * SMS + col] = packbf(l0, l1);
        }
    }
    __syncthreads();

    // ================= Phase 2: OUT[128][2048] = H @ B^T =================
    // load A-operand (H) fragments once: K=64 -> 4 k-steps
    uint32_t hh[4][4], hl[4][4];
#pragma unroll
    for (int kk = 0; kk < 4; ++kk) {
        uint32_t abase = (w * 16 * SMS + kk * 16) * 2;
        ldsm4(hh[kk], sb + HH_H * 2 + abase + offA);
        ldsm4(hl[kk], sb + HL_H * 2 + abase + offA);
    }

    const int r0 = w * 16 + (lane >> 2);
    const int cb = (lane & 3) * 2;
    const int tA = s_tok[r0];
    const int tB = s_tok[r0 + 8];

    for (int d0 = 0; d0 < ND; d0 += DC) {
        // stage B chunk bf16 hi/lo [128 d][SMS] (rows contiguous in r)
#pragma unroll
        for (int i = tid; i < DC * (NR / 4); i += 256) {
            int d = i >> 4, c = (i & 15) << 2;
            *(uint2*)&smh[BH_H + d * SMS + c] = *(const uint2*)(Bh + (d0 + d) * NR + c);
            *(uint2*)&smh[BL_H + d * SMS + c] = *(const uint2*)(Bl + (d0 + d) * NR + c);
        }
        __syncthreads();

        float acc2[16][4];
#pragma unroll
        for (int f = 0; f < 16; ++f)
#pragma unroll
            for (int j = 0; j < 4; ++j) acc2[f][j] = 0.f;

#pragma unroll
        for (int g = 0; g < 8; ++g) {              // n-groups of 16 (d dim)
#pragma unroll
            for (int kk = 0; kk < 4; ++kk) {
                uint32_t bh[4], bl[4];
                uint32_t bbase = (g * 16 * SMS + kk * 16) * 2;
                ldsm4(bh, sb + BH_H * 2 + bbase + offB);
                ldsm4(bl, sb + BL_H * 2 + bbase + offB);
                mma_bf16(acc2[2 * g], hh[kk], bh[0], bh[1]);
                mma_bf16(acc2[2 * g], hh[kk], bl[0], bl[1]);
                mma_bf16(acc2[2 * g], hl[kk], bh[0], bh[1]);
                mma_bf16(acc2[2 * g + 1], hh[kk], bh[2], bh[3]);
                mma_bf16(acc2[2 * g + 1], hh[kk], bl[2], bl[3]);
                mma_bf16(acc2[2 * g + 1], hl[kk], bh[2], bh[3]);
            }
        }

        // store: float2 per fragment row
#pragma unroll
        for (int f = 0; f < 16; ++f) {
            int col = d0 + 8 * f + cb;
            if (tA >= 0)
                *(float2*)(out + (size_t)tA * ND + col) = make_float2(acc2[f][0], acc2[f][1]);
            if (tB >= 0)
                *(float2*)(out + (size_t)tB * ND + col) = make_float2(acc2[f][2], acc2[f][3]);
        }
        __syncthreads();
    }
}

extern "C" void kernel_launch(void* const* d_in, const int* in_sizes, int n_in,
                              void* d_out, int out_size) {
    const float* x   = (const float*)d_in[0];
    const float* Aw  = (const float*)d_in[1];
    const float* Bw  = (const float*)d_in[2];
    const int*   idx = (const int*)d_in[3];
    float* out = (float*)d_out;

    cudaFuncSetAttribute(k_lora, cudaFuncAttributeMaxDynamicSharedMemorySize, SMEM_BYTES);

    k_init<<<(ORDER_SZ + 1023) / 1024, 1024>>>();
    k_hist<<<NT / 1024, 1024>>>(idx);
    k_scan<<<1, 1>>>();
    k_scatter<<<NT / 1024, 1024>>>(idx);
    k_convW<<<WSZ / 256, 256>>>(Aw, Bw);
    k_lora<<<MAX_TILES, 256, SMEM_BYTES>>>(x, out);
}

// round 4
// speedup vs baseline: 3.1497x; 2.0296x over previous
#include <cuda_runtime.h>
#include <cuda_bf16.h>
#include <cstdint>

// Problem constants
#define NE 8
#define NR 64
#define ND 2048
#define NT 16384            // B*S tokens
#define TILE_M 128
#define ORDER_SZ (NT + NE * TILE_M)
#define MAX_TILES (ORDER_SZ / TILE_M)     // 136
#define WSZ (NE * NR * ND)                // weight elems per tensor
#define KC 64                              // phase-1 K chunk
#define DC 128                             // phase-2 D chunk
#define SMS 72                             // smem row stride in halves (bank-safe for ldmatrix)

// smem layout (half indices). Double-buffered x/A (phase1); B (phase2) aliases x region.
#define XH0 0
#define XH1 (XH0 + TILE_M * SMS)
#define XL0 (XH1 + TILE_M * SMS)
#define XL1 (XL0 + TILE_M * SMS)
#define AH0 (XL1 + TILE_M * SMS)
#define AH1 (AH0 + NR * SMS)
#define AL0 (AH1 + NR * SMS)
#define AL1 (AL0 + NR * SMS)
#define HH_ (AL1 + NR * SMS)
#define HL_ (HH_ + TILE_M * SMS)
#define SMEM_HALVES (HL_ + TILE_M * SMS)  // 73728
#define SMEM_BYTES (SMEM_HALVES * 2)      // 147456
#define BH0 XH0
#define BH1 XH1
#define BL0 XL0
#define BL1 XL1

// -------- grouping state + split weights (device globals) --------
__device__ int g_counts[NE];
__device__ int g_base[NE];
__device__ int g_order[ORDER_SZ];
__device__ int g_tile_expert[MAX_TILES];
__device__ __nv_bfloat16 g_Ah[WSZ], g_Al[WSZ];
__device__ __nv_bfloat16 g_Bh[WSZ], g_Bl[WSZ];

__global__ void k_init() {
    int i = blockIdx.x * blockDim.x + threadIdx.x;
    if (i < ORDER_SZ) g_order[i] = -1;
    if (i < NE) g_counts[i] = 0;
    if (i < MAX_TILES) g_tile_expert[i] = -1;
}

__global__ void k_hist(const int* __restrict__ idx) {
    __shared__ int s_cnt[NE];
    int tid = threadIdx.x;
    if (tid < NE) s_cnt[tid] = 0;
    __syncthreads();
    int t = blockIdx.x * blockDim.x + tid;
    atomicAdd(&s_cnt[idx[t]], 1);
    __syncthreads();
    if (tid < NE && s_cnt[tid] > 0) atomicAdd(&g_counts[tid], s_cnt[tid]);
}

__global__ void k_scan() {
    int off = 0, tile = 0;
    for (int e = 0; e < NE; ++e) {
        g_base[e] = off;
        int nt = (g_counts[e] + TILE_M - 1) / TILE_M;
        for (int j = 0; j < nt; ++j) g_tile_expert[tile++] = e;
        off += nt * TILE_M;
    }
}

__global__ void k_scatter(const int* __restrict__ idx) {
    __shared__ int s_cnt[NE], s_base[NE];
    int tid = threadIdx.x;
    if (tid < NE) s_cnt[tid] = 0;
    __syncthreads();
    int t = blockIdx.x * blockDim.x + tid;
    int e = idx[t];
    int lp = atomicAdd(&s_cnt[e], 1);
    __syncthreads();
    if (tid < NE) s_base[tid] = (s_cnt[tid] > 0) ? atomicAdd(&g_base[tid], s_cnt[tid]) : 0;
    __syncthreads();
    g_order[s_base[e] + lp] = t;
}

__global__ void k_convW(const float* __restrict__ Aw, const float* __restrict__ Bw) {
    int i = blockIdx.x * blockDim.x + threadIdx.x;
    if (i >= WSZ) return;
    float a = Aw[i];
    __nv_bfloat16 ah = __float2bfloat16(a);
    g_Ah[i] = ah;
    g_Al[i] = __float2bfloat16(a - __bfloat162float(ah));
    float b = Bw[i];
    __nv_bfloat16 bh = __float2bfloat16(b);
    g_Bh[i] = bh;
    g_Bl[i] = __float2bfloat16(b - __bfloat162float(bh));
}

// -------- helpers --------
__device__ __forceinline__ void ldsm4(uint32_t* r, uint32_t addr) {
    asm volatile("ldmatrix.sync.aligned.m8n8.x4.shared.b16 {%0,%1,%2,%3}, [%4];"
                 : "=r"(r[0]), "=r"(r[1]), "=r"(r[2]), "=r"(r[3]) : "r"(addr));
}
__device__ __forceinline__ void mma_bf16(float* c, const uint32_t* a, uint32_t b0, uint32_t b1) {
    asm volatile("mma.sync.aligned.m16n8k16.row.col.f32.bf16.bf16.f32 "
                 "{%0,%1,%2,%3}, {%4,%5,%6,%7}, {%8,%9}, {%0,%1,%2,%3};"
                 : "+f"(c[0]), "+f"(c[1]), "+f"(c[2]), "+f"(c[3])
                 : "r"(a[0]), "r"(a[1]), "r"(a[2]), "r"(a[3]), "r"(b0), "r"(b1));
}
__device__ __forceinline__ uint32_t packbf(__nv_bfloat16 a, __nv_bfloat16 b) {
    __nv_bfloat162 t(a, b);
    return *(uint32_t*)&t;
}
__device__ __forceinline__ void split2(float v, __nv_bfloat16& h, __nv_bfloat16& l) {
    h = __float2bfloat16(v);
    l = __float2bfloat16(v - __bfloat162float(h));
}
__device__ __forceinline__ void cp16(uint32_t dst, const void* src) {
    asm volatile("cp.async.cg.shared.global [%0], [%1], 16;" :: "r"(dst), "l"(src));
}
#define CP_COMMIT() asm volatile("cp.async.commit_group;" ::: "memory")
#define CP_WAIT1()  asm volatile("cp.async.wait_group 1;" ::: "memory")

// -------- fused pipelined tile kernel --------
__global__ __launch_bounds__(256, 1) void k_lora(
    const float* __restrict__ x, float* __restrict__ out) {
    extern __shared__ __nv_bfloat16 smh[];
    __shared__ int s_tok[TILE_M];

    const int e = g_tile_expert[blockIdx.x];
    if (e < 0) return;
    const int tid = threadIdx.x;
    const int w = tid >> 5;
    const int lane = tid & 31;
    if (tid < TILE_M) s_tok[tid] = g_order[blockIdx.x * TILE_M + tid];
    __syncthreads();

    const uint32_t sb = (uint32_t)__cvta_generic_to_shared(smh);
    const int within = lane & 7, mat = lane >> 3;
    const uint32_t offA = (((within + ((mat & 1) << 3)) * SMS) + ((mat >> 1) << 3)) * 2;
    const uint32_t offB = (((within + ((mat >> 1) << 3)) * SMS) + ((mat & 1) << 3)) * 2;

    const __nv_bfloat16* Ah = g_Ah + e * NR * ND;
    const __nv_bfloat16* Al = g_Al + e * NR * ND;
    const __nv_bfloat16* Bh = g_Bh + e * ND * NR;
    const __nv_bfloat16* Bl = g_Bl + e * ND * NR;

    // ================= Phase 1: H[128][64] = X @ A^T (pipelined) =================
    float acc[8][4];
#pragma unroll
    for (int f = 0; f < 8; ++f)
#pragma unroll
        for (int j = 0; j < 4; ++j) acc[f][j] = 0.f;

    float4 xr[2][8];
    // prologue: x chunk 0 -> regs, A chunk 0 -> buffers 0 via cp.async
#pragma unroll
    for (int j = 0; j < 8; ++j) {
        int i = tid + j * 256;
        int m = i >> 4, cc = (i & 15) << 2;
        int t = s_tok[m];
        xr[0][j] = (t >= 0) ? *(const float4*)(x + (size_t)t * ND + cc)
                            : make_float4(0.f, 0.f, 0.f, 0.f);
    }
#pragma unroll
    for (int j = 0; j < 2; ++j) {
        int i = tid + j * 256;
        int r = i >> 3, c8 = (i & 7) << 3;
        cp16(sb + (uint32_t)(AH0 + r * SMS + c8) * 2, Ah + r * ND + c8);
        cp16(sb + (uint32_t)(AL0 + r * SMS + c8) * 2, Al + r * ND + c8);
    }
    CP_COMMIT();

#pragma unroll 2
    for (int c = 0; c < ND / KC; ++c) {
        const int cur = c & 1;
        const uint32_t xh_b = cur ? XH1 : XH0, xl_b = cur ? XL1 : XL0;
        const uint32_t ah_b = cur ? AH1 : AH0, al_b = cur ? AL1 : AL0;

        // store current x chunk (convert f32 -> bf16 hi/lo)
#pragma unroll
        for (int j = 0; j < 8; ++j) {
            int i = tid + j * 256;
            int m = i >> 4, cc = (i & 15) << 2;
            float4 v = xr[cur][j];
            __nv_bfloat16 h0, l0, h1, l1, h2, l2, h3, l3;
            split2(v.x, h0, l0); split2(v.y, h1, l1);
            split2(v.z, h2, l2); split2(v.w, h3, l3);
            *(uint2*)&smh[xh_b + m * SMS + cc] = make_uint2(packbf(h0, h1), packbf(h2, h3));
            *(uint2*)&smh[xl_b + m * SMS + cc] = make_uint2(packbf(l0, l1), packbf(l2, l3));
        }
        // prefetch next chunk
        if (c + 1 < ND / KC) {
            const int k0n = (c + 1) * KC;
#pragma unroll
            for (int j = 0; j < 8; ++j) {
                int i = tid + j * 256;
                int m = i >> 4, cc = (i & 15) << 2;
                int t = s_tok[m];
                xr[cur ^ 1][j] = (t >= 0) ? *(const float4*)(x + (size_t)t * ND + k0n + cc)
                                          : make_float4(0.f, 0.f, 0.f, 0.f);
            }
            const uint32_t ahn = cur ? AH0 : AH1, aln = cur ? AL0 : AL1;
#pragma unroll
            for (int j = 0; j < 2; ++j) {
                int i = tid + j * 256;
                int r = i >> 3, c8 = (i & 7) << 3;
                cp16(sb + (uint32_t)(ahn + r * SMS + c8) * 2, Ah + r * ND + k0n + c8);
                cp16(sb + (uint32_t)(aln + r * SMS + c8) * 2, Al + r * ND + k0n + c8);
            }
        }
        CP_COMMIT();
        CP_WAIT1();
        __syncthreads();

#pragma unroll
        for (int kk = 0; kk < KC / 16; ++kk) {
            uint32_t ah[4], al[4];
            uint32_t abase = (uint32_t)(w * 16 * SMS + kk * 16) * 2;
            ldsm4(ah, sb + xh_b * 2 + abase + offA);
            ldsm4(al, sb + xl_b * 2 + abase + offA);
#pragma unroll
            for (int g = 0; g < 4; ++g) {
                uint32_t bh[4], bl[4];
                uint32_t bbase = (uint32_t)(g * 16 * SMS + kk * 16) * 2;
                ldsm4(bh, sb + ah_b * 2 + bbase + offB);
                ldsm4(bl, sb + al_b * 2 + bbase + offB);
                mma_bf16(acc[2 * g], ah, bh[0], bh[1]);
                mma_bf16(acc[2 * g], ah, bl[0], bl[1]);
                mma_bf16(acc[2 * g], al, bh[0], bh[1]);
                mma_bf16(acc[2 * g + 1], ah, bh[2], bh[3]);
                mma_bf16(acc[2 * g + 1], ah, bl[2], bl[3]);
                mma_bf16(acc[2 * g + 1], al, bh[2], bh[3]);
            }
        }
        __syncthreads();
    }

    // spill H -> smem bf16 hi/lo
    {
        int r0 = w * 16 + (lane >> 2);
        int cb = (lane & 3) * 2;
#pragma unroll
        for (int f = 0; f < 8; ++f) {
            int col = 8 * f + cb;
            __nv_bfloat16 h0, l0, h1, l1;
            split2(acc[f][0], h0, l0); split2(acc[f][1], h1, l1);
            *(uint32_t*)&smh[HH_ + r0 * SMS + col] = packbf(h0, h1);
            *(uint32_t*)&smh[HL_ + r0 * SMS + col] = packbf(l0, l1);
            split2(acc[f][2], h0, l0); split2(acc[f][3], h1, l1);
            *(uint32_t*)&smh[HH_ + (r0 + 8) * SMS + col] = packbf(h0, h1);
            *(uint32_t*)&smh[HL_ + (r0 + 8) * SMS + col] = packbf(l0, l1);
        }
    }
    __syncthreads();

    // ================= Phase 2: OUT[128][2048] = H @ B^T (pipelined) =================
    uint32_t hh[4][4], hl[4][4];
#pragma unroll
    for (int kk = 0; kk < 4; ++kk) {
        uint32_t abase = (uint32_t)(w * 16 * SMS + kk * 16) * 2;
        ldsm4(hh[kk], sb + HH_ * 2 + abase + offA);
        ldsm4(hl[kk], sb + HL_ * 2 + abase + offA);
    }
    __syncthreads();   // all H reads done before B cp.async overwrites aliased region? (B aliases X, not H — barrier keeps ordering tight anyway)

    const int r0 = w * 16 + (lane >> 2);
    const int cb = (lane & 3) * 2;
    const int tA = s_tok[r0];
    const int tB = s_tok[r0 + 8];

    // prologue: B chunk 0 -> buffers 0
#pragma unroll
    for (int j = 0; j < 4; ++j) {
        int i = tid + j * 256;
        int d = i >> 3, c8 = (i & 7) << 3;
        cp16(sb + (uint32_t)(BH0 + d * SMS + c8) * 2, Bh + d * NR + c8);
        cp16(sb + (uint32_t)(BL0 + d * SMS + c8) * 2, Bl + d * NR + c8);
    }
    CP_COMMIT();

#pragma unroll 2
    for (int dcb = 0; dcb < ND / DC; ++dcb) {
        const int cur = dcb & 1;
        const uint32_t bh_b = cur ? BH1 : BH0, bl_b = cur ? BL1 : BL0;
        const int d0 = dcb * DC;

        if (dcb + 1 < ND / DC) {
            const int d0n = (dcb + 1) * DC;
            const uint32_t bhn = cur ? BH0 : BH1, bln = cur ? BL0 : BL1;
#pragma unroll
            for (int j = 0; j < 4; ++j) {
                int i = tid + j * 256;
                int d = i >> 3, c8 = (i & 7) << 3;
                cp16(sb + (uint32_t)(bhn + d * SMS + c8) * 2, Bh + (d0n + d) * NR + c8);
                cp16(sb + (uint32_t)(bln + d * SMS + c8) * 2, Bl + (d0n + d) * NR + c8);
            }
        }
        CP_COMMIT();
        CP_WAIT1();
        __syncthreads();

        float acc2[16][4];
#pragma unroll
        for (int f = 0; f < 16; ++f)
#pragma unroll
            for (int j = 0; j < 4; ++j) acc2[f][j] = 0.f;

#pragma unroll
        for (int g = 0; g < 8; ++g) {
#pragma unroll
            for (int kk = 0; kk < 4; ++kk) {
                uint32_t bh[4], bl[4];
                uint32_t bbase = (uint32_t)(g * 16 * SMS + kk * 16) * 2;
                ldsm4(bh, sb + bh_b * 2 + bbase + offB);
                ldsm4(bl, sb + bl_b * 2 + bbase + offB);
                mma_bf16(acc2[2 * g], hh[kk], bh[0], bh[1]);
                mma_bf16(acc2[2 * g], hh[kk], bl[0], bl[1]);
                mma_bf16(acc2[2 * g], hl[kk], bh[0], bh[1]);
                mma_bf16(acc2[2 * g + 1], hh[kk], bh[2], bh[3]);
                mma_bf16(acc2[2 * g + 1], hh[kk], bl[2], bl[3]);
                mma_bf16(acc2[2 * g + 1], hl[kk], bh[2], bh[3]);
            }
        }

#pragma unroll
        for (int f = 0; f < 16; ++f) {
            int col = d0 + 8 * f + cb;
            if (tA >= 0)
                *(float2*)(out + (size_t)tA * ND + col) = make_float2(acc2[f][0], acc2[f][1]);
            if (tB >= 0)
                *(float2*)(out + (size_t)tB * ND + col) = make_float2(acc2[f][2], acc2[f][3]);
        }
        __syncthreads();
    }
}

extern "C" void kernel_launch(void* const* d_in, const int* in_sizes, int n_in,
                              void* d_out, int out_size) {
    const float* x   = (const float*)d_in[0];
    const float* Aw  = (const float*)d_in[1];
    const float* Bw  = (const float*)d_in[2];
    const int*   idx = (const int*)d_in[3];
    float* out = (float*)d_out;

    cudaFuncSetAttribute(k_lora, cudaFuncAttributeMaxDynamicSharedMemorySize, SMEM_BYTES);

    k_init<<<(ORDER_SZ + 1023) / 1024, 1024>>>();
    k_hist<<<NT / 1024, 1024>>>(idx);
    k_scan<<<1, 1>>>();
    k_scatter<<<NT / 1024, 1024>>>(idx);
    k_convW<<<WSZ / 256, 256>>>(Aw, Bw);
    k_lora<<<MAX_TILES, 256, SMEM_BYTES>>>(x, out);
}